// round 13
// baseline (speedup 1.0000x reference)
#include <cuda_runtime.h>
#include <cstdint>
#include <math.h>

// BinaryTreeLatentVariable: N_LEAVES=1024, L=16, C=4.
// out[node,o] = parent[node,o] + sL + sR
//             + log( sum_{i,j} expT[o,i,j] * exp(L[i]-sL) * exp(R[j]-sR) )
// Persistent kernel, 256 CTAs x 512 threads. R13: each CTA = two independent
// 8-warp groups (named barriers, private smem buffers, private dataflow
// arrivals) so one group's FFMA2 mainloop overlaps the other's setup/epilogue.
// Per level each group runs exactly ONE chunk (<=16 nodes).

#define OC 64
#define OG 16          // o-groups; each CTA owns 4 outputs
#define XS 16          // node slices
#define NCTA (OG * XS) // 256
#define ELS 20         // eLs row stride: 16B-aligned, 4-way STS conflicts

__device__ float g_ET[OC * 4096];      // 1 MB: exp(trans) repacked [o][i][j]
__device__ float g_buf[1023 * OC];     // per-level buffers, no reuse
__device__ unsigned int g_cnt[160];    // [level][slice], target 32 (16 CTA x 2 grp)

// ---- packed f32x2 helpers (FFMA2) ------------------------------------------
__device__ __forceinline__ unsigned long long pack2(float x, float y) {
    unsigned long long r;
    asm("mov.b64 %0, {%1, %2};" : "=l"(r) : "f"(x), "f"(y));
    return r;
}
__device__ __forceinline__ void unpack2(unsigned long long v, float& x, float& y) {
    asm("mov.b64 {%0, %1}, %2;" : "=f"(x), "=f"(y) : "l"(v));
}
__device__ __forceinline__ void ffma2(unsigned long long& d,
                                      unsigned long long a, unsigned long long b) {
    asm("fma.rn.f32x2 %0, %1, %2, %0;" : "+l"(d) : "l"(a), "l"(b));
}

// ---- group barrier: 256 threads, barrier id 1+grp --------------------------
__device__ __forceinline__ void bar_grp(int grp) {
    asm volatile("bar.sync %0, 256;" :: "r"(grp + 1) : "memory");
}

// ---- butterfly multi-value warp allreduce ----------------------------------
template <int NV>
__device__ __forceinline__ float butterflyN(float s[NV], int lane) {
    #pragma unroll
    for (int k = 0; k < 5; k++) {
        const int w = 16 >> k;
        const int m = (NV / 2) >> k;
        if (m >= 1) {
            const bool up = (lane & w) != 0;
            #pragma unroll
            for (int i = 0; i < m; i++) {
                float t = up ? s[i] : s[i + m];
                float r = __shfl_xor_sync(0xffffffffu, t, w);
                s[i] = (up ? s[i + m] : s[i]) + r;
            }
        } else {
            s[0] += __shfl_xor_sync(0xffffffffu, s[0], w);
        }
    }
    return s[0];
}
template <int NV>
__device__ __forceinline__ int butterfly_idx(int lane) {
    int idx = 0;
    #pragma unroll
    for (int k = 0; k < 5; k++) {
        const int m = (NV / 2) >> k;
        if (m >= 1) idx += ((lane >> (4 - k)) & 1) * m;
    }
    return idx;
}

// ---- Prologue: ET[o][i][j] = exp(trans[...]); reset all counters -----------
__global__ void expT_kernel(const float* __restrict__ trans) {
    if (blockIdx.x == 0 && threadIdx.x < 160) g_cnt[threadIdx.x] = 0u;
    int idx = blockIdx.x * 256 + threadIdx.x;   // 0 .. 262143
    int o = idx >> 12, i = (idx >> 6) & 63, j = idx & 63;
    int lp = o >> 2, cp = o & 3;
    int ll = i >> 2, cl = i & 3;
    int lr = j >> 2, cr = j & 3;
    int src = ((((lp * 16 + ll) * 16 + lr) * 4 + cp) * 4 + cl) * 4 + cr;
    g_ET[idx] = expf(trans[src]);
}

// ---- prefetch helpers (group-local) ----------------------------------------
template <int NBX>
__device__ __forceinline__ void prefetch_children(
    float* P, int gs, int ge, const float* __restrict__ child,
    int wg, int lane)
{
    #pragma unroll
    for (int k = 0; k < 2; k++) {
        const int nb = wg + k * 8;
        const int node = gs + nb;
        if (nb < NBX && node < ge) {
            const float* L = child + (size_t)(2 * node) * OC;
            P[4 * k + 0] = L[lane];       P[4 * k + 1] = L[lane + 32];
            P[4 * k + 2] = L[lane + 64];  P[4 * k + 3] = L[lane + 96];
        }
    }
}
template <int NBX>
__device__ __forceinline__ void prefetch_parent(
    float& pPar, int gs, int ge, const float* __restrict__ parent,
    int og, int gtid)
{
    if (gtid < 4 * NBX) {
        const int nb = gtid & (NBX - 1);
        const int node = gs + nb;
        if (node < ge)
            pPar = parent[(size_t)node * OC + og * 4 + gtid / NBX];
    }
}

// ---------------------------------------------------------------------------
// One group-chunk of NBX nodes. 8 warps: warp wg -> output g=wg>>1 of the
// CTA's four, i-half = wg&1 (32 i's). Lane owns j = {2*lane, 2*lane+1}.
// ---------------------------------------------------------------------------
template <int NBX>
__device__ __forceinline__ void do_chunk(
    int gs, int ge,
    float* __restrict__ out, const float* ET_s,
    float* eLb, float* eRb, float* baseb, float* partb,
    const float* P, float pcur,
    int og, int gtid, int wg, int lane, int g, int half, int grp)
{
    constexpr int NP = NBX / 2;

    // ---- setup: prefetched children -> cheap shift -> exp -> smem ----
    #pragma unroll
    for (int k = 0; k < 2; k++) {
        const int nb = wg + k * 8;
        if (nb >= NBX) break;
        const int node = gs + nb;
        if (node < ge) {
            float sL = __shfl_sync(0xffffffffu, fmaxf(P[4 * k + 0], P[4 * k + 1]), 0);
            float sR = __shfl_sync(0xffffffffu, fmaxf(P[4 * k + 2], P[4 * k + 3]), 0);
            eLb[lane * ELS + nb]        = __expf(P[4 * k + 0] - sL);
            eLb[(lane + 32) * ELS + nb] = __expf(P[4 * k + 1] - sL);
            eRb[nb * 64 + lane]         = __expf(P[4 * k + 2] - sR);
            eRb[nb * 64 + lane + 32]    = __expf(P[4 * k + 3] - sR);
            if (lane == 0) baseb[nb] = sL + sR;
        } else {
            eLb[lane * ELS + nb] = 0.0f;  eLb[(lane + 32) * ELS + nb] = 0.0f;
            eRb[nb * 64 + lane]  = 0.0f;  eRb[nb * 64 + lane + 32]    = 0.0f;
            if (lane == 0) baseb[nb] = 0.0f;
        }
    }
    bar_grp(grp);

    // ---- mainloop: 32 i's, FFMA2 over NBX accumulator pairs ----
    unsigned long long A0[NP], A1[NP];
    #pragma unroll
    for (int p = 0; p < NP; p++) { A0[p] = 0ull; A1[p] = 0ull; }

    const float2* ets = reinterpret_cast<const float2*>(ET_s + (size_t)g * 4096);
    const int ib = half * 32;
    #pragma unroll 16
    for (int ii = 0; ii < 32; ii++) {
        const int i = ib + ii;
        float2 e = ets[i * 32 + lane];               // ET[o, i, 2lane..+1]
        unsigned long long exx = pack2(e.x, e.x);
        unsigned long long eyy = pack2(e.y, e.y);
        const ulonglong2* el2 = reinterpret_cast<const ulonglong2*>(eLb + i * ELS);
        #pragma unroll
        for (int pp = 0; pp < NBX / 4; pp++) {
            ulonglong2 w = el2[pp];                  // 4 nodes, one LDS.128
            ffma2(A0[2 * pp],     exx, w.x);
            ffma2(A1[2 * pp],     eyy, w.x);
            ffma2(A0[2 * pp + 1], exx, w.y);
            ffma2(A1[2 * pp + 1], eyy, w.y);
        }
    }

    // ---- fold eR, butterfly-reduce NBX sums, one predicated STS ----
    float s[NBX];
    #pragma unroll
    for (int p = 0; p < NP; p++) {
        float a0x, a0y, a1x, a1y;
        unpack2(A0[p], a0x, a0y);
        unpack2(A1[p], a1x, a1y);
        float2 er0 = reinterpret_cast<const float2*>(eRb + (2 * p) * 64)[lane];
        float2 er1 = reinterpret_cast<const float2*>(eRb + (2 * p + 1) * 64)[lane];
        s[2 * p]     = a0x * er0.x + a1x * er0.y;
        s[2 * p + 1] = a0y * er1.x + a1y * er1.y;
    }
    float v = butterflyN<NBX>(s, lane);
    const int idx = butterfly_idx<NBX>(lane);
    if ((lane & (32 / NBX - 1)) == 0)
        partb[(g * 16 + idx) * 2 + half] = v;
    bar_grp(grp);

    // ---- epilogue: combine halves, log, write (parent prefetched) ----
    if (gtid < 4 * NBX) {
        const int gg = gtid / NBX, nb = gtid & (NBX - 1);
        const int node = gs + nb;
        if (node < ge) {
            float vv = partb[(gg * 16 + nb) * 2] + partb[(gg * 16 + nb) * 2 + 1];
            out[(size_t)node * OC + og * 4 + gg] = pcur + baseb[nb] + __logf(vv);
        }
    }
}

// ---- counter wait (group leader) -------------------------------------------
__device__ __forceinline__ void wait_cnt32(const unsigned int* c) {
    unsigned int cur;
    do {
        asm volatile("ld.acquire.gpu.global.u32 %0, [%1];"
                     : "=r"(cur) : "l"(c) : "memory");
    } while (cur < 32u);
}

// ---------------------------------------------------------------------------
// Persistent tree kernel: slice-local dataflow, two phase-skewed groups/CTA.
// ---------------------------------------------------------------------------
__global__ __launch_bounds__(512, 2) void tree_kernel(
    const float* __restrict__ node_state, float* __restrict__ d_out)
{
    extern __shared__ float smem[];
    float* ET_s   = smem;                  // 16384 floats (64 KB)
    float* eLs    = smem + 16384;          // 2 grp x [64][ELS]
    float* eRs    = eLs + 2 * 64 * ELS;    // 2 grp x [16][64]
    float* base_s = eRs + 2048;            // 2 grp x 16
    float* part   = base_s + 32;           // 2 grp x 128

    const int tid  = threadIdx.x;
    const int warp = tid >> 5;
    const int lane = tid & 31;
    const int og   = blockIdx.x & (OG - 1);
    const int xs   = blockIdx.x >> 4;      // 0..15
    const int grp  = warp >> 3;            // 0 or 1
    const int wg   = warp & 7;             // warp within group
    const int gtid = tid & 255;            // thread within group
    const int g    = wg >> 1;              // output within CTA's four
    const int half = wg & 1;               // i-half

    float* eLb   = eLs    + grp * (64 * ELS);
    float* eRb   = eRs    + grp * 1024;
    float* baseb = base_s + grp * 16;
    float* partb = part   + grp * 128;

    // ---- one-time ET slice fill: 64 KB via cp.async (whole CTA) ----
    {
        unsigned int dst;
        asm("{ .reg .u64 t; cvta.to.shared.u64 t, %1; cvt.u32.u64 %0, t; }"
            : "=r"(dst) : "l"(ET_s));
        const float4* src = reinterpret_cast<const float4*>(g_ET)
                            + (size_t)og * 4096;
        #pragma unroll
        for (int t = 0; t < 8; t++) {
            int e = tid + t * 512;
            asm volatile("cp.async.cg.shared.global [%0], [%1], 16;"
                         :: "r"(dst + 16u * (unsigned)e), "l"(src + e));
        }
        asm volatile("cp.async.commit_group;");
        asm volatile("cp.async.wait_group 0;");
    }
    __syncthreads();   // one CTA-wide sync; groups independent afterwards

    const float* leaves = node_state + (size_t)1023 * OC;
    float P[8];
    float pPar = 0.0f;

    #pragma unroll 1
    for (int l = 0; l < 10; l++) {
        const int n   = 512 >> l;
        const int npc = (n >= XS) ? (n / XS) : 1;
        const int nstart = xs * npc;
        if (nstart >= n) return;           // idle CTA: nobody waits on us
        const int nend = (nstart + npc < n) ? (nstart + npc) : n;

        // group range: split the CTA's nodes in half
        const int gcount = nend - nstart;
        const int halfc  = gcount >> 1;
        const int gs = (grp == 0) ? nstart : nstart + (gcount - halfc);
        const int ge = (grp == 0) ? nstart + (gcount - halfc) : nend;
        const int size = ge - gs;

        const float* child = (l == 0) ? leaves
                           : g_buf + (size_t)(1024 - (2048 >> l)) * OC;
        float* out = (l == 9) ? d_out
                   : g_buf + (size_t)(1024 - (1024 >> l)) * OC;
        const float* parent = node_state + (size_t)(n - 1) * OC;

        // ---- parent prefetch (pure input) overlaps the wait ----
        if (size >= 16)      prefetch_parent<16>(pPar, gs, ge, parent, og, gtid);
        else if (size == 8)  prefetch_parent<8 >(pPar, gs, ge, parent, og, gtid);
        else if (size > 0)   prefetch_parent<4 >(pPar, gs, ge, parent, og, gtid);

        // ---- dataflow wait: only this slice's producers (group leader) ----
        if (l > 0) {
            if (gtid == 0) {
                if (n >= 16) {
                    wait_cnt32(&g_cnt[(l - 1) * 16 + xs]);
                } else {
                    wait_cnt32(&g_cnt[(l - 1) * 16 + 2 * xs]);
                    wait_cnt32(&g_cnt[(l - 1) * 16 + 2 * xs + 1]);
                }
            }
            bar_grp(grp);
        }

        // ---- the group's single chunk for this level ----
        if (size >= 16) {
            prefetch_children<16>(P, gs, ge, child, wg, lane);
            do_chunk<16>(gs, ge, out, ET_s, eLb, eRb, baseb, partb,
                         P, pPar, og, gtid, wg, lane, g, half, grp);
        } else if (size == 8) {
            prefetch_children<8>(P, gs, ge, child, wg, lane);
            do_chunk<8>(gs, ge, out, ET_s, eLb, eRb, baseb, partb,
                        P, pPar, og, gtid, wg, lane, g, half, grp);
        } else if (size > 0) {
            prefetch_children<4>(P, gs, ge, child, wg, lane);
            do_chunk<4>(gs, ge, out, ET_s, eLb, eRb, baseb, partb,
                        P, pPar, og, gtid, wg, lane, g, half, grp);
        }

        // ---- arrival: group's writes done -> release one count ----
        if (l < 9) {
            bar_grp(grp);
            if (gtid == 0) {
                asm volatile("red.release.gpu.global.add.u32 [%0], 1;"
                             :: "l"(&g_cnt[l * 16 + xs]) : "memory");
            }
        }
    }
}

// ---------------------------------------------------------------------------
// Host side
// ---------------------------------------------------------------------------
#define TREE_SMEM ((16384 + 2 * 64 * ELS + 2048 + 32 + 256) * 4)

extern "C" void kernel_launch(void* const* d_in, const int* in_sizes, int n_in,
                              void* d_out, int out_size)
{
    const float* node_state = (const float*)d_in[0];
    const float* trans      = (const float*)d_in[1];
    if (n_in >= 2 && in_sizes[0] == 262144) {   // defensive input identification
        const float* t = node_state; node_state = trans; trans = t;
    }

    cudaFuncSetAttribute(tree_kernel,
                         cudaFuncAttributeMaxDynamicSharedMemorySize, TREE_SMEM);

    expT_kernel<<<1024, 256>>>(trans);
    tree_kernel<<<NCTA, 512, TREE_SMEM>>>(node_state, (float*)d_out);
}